// round 15
// baseline (speedup 1.0000x reference)
#include <cuda_runtime.h>
#include <cuda_fp16.h>
#include <cstdint>

#define T_SEQ 4096
#define D_MODEL 1024

// ---------------- scratch (__device__ globals; no allocs allowed) ----------
__device__ __half g_xh[T_SEQ * D_MODEL];
__device__ __half g_Wqh[D_MODEL * D_MODEL];
__device__ __half g_Wkh[D_MODEL * D_MODEL];
__device__ __half g_Qh[T_SEQ * D_MODEL];
__device__ __half g_Kh[T_SEQ * D_MODEL];

// ---------------- helpers ---------------------------------------------------
__device__ __forceinline__ uint32_t smem_u32(const void* p) {
    uint32_t a;
    asm("{ .reg .u64 t; cvta.to.shared.u64 t, %1; cvt.u32.u64 %0, t; }" : "=r"(a) : "l"(p));
    return a;
}
__device__ __forceinline__ void cp_async16(uint32_t s, const void* g) {
    asm volatile("cp.async.cg.shared.global [%0], [%1], 16;" :: "r"(s), "l"(g));
}
__device__ __forceinline__ void cp_commit() {
    asm volatile("cp.async.commit_group;" ::: "memory");
}
template <int N> __device__ __forceinline__ void cp_wait() {
    asm volatile("cp.async.wait_group %0;" :: "n"(N) : "memory");
}
__device__ __forceinline__ void ldsm4(uint32_t* r, uint32_t addr) {
    asm volatile("ldmatrix.sync.aligned.m8n8.x4.shared.b16 {%0,%1,%2,%3}, [%4];"
                 : "=r"(r[0]), "=r"(r[1]), "=r"(r[2]), "=r"(r[3]) : "r"(addr));
}
__device__ __forceinline__ void mma16816(float* c, const uint32_t* a, uint32_t b0, uint32_t b1) {
    asm volatile(
        "mma.sync.aligned.m16n8k16.row.col.f32.f16.f16.f32 "
        "{%0,%1,%2,%3}, {%4,%5,%6,%7}, {%8,%9}, {%0,%1,%2,%3};"
        : "+f"(c[0]), "+f"(c[1]), "+f"(c[2]), "+f"(c[3])
        : "r"(a[0]), "r"(a[1]), "r"(a[2]), "r"(a[3]), "r"(b0), "r"(b1));
}

// ---------------- Threefry-2x32-20 (JAX partitionable path) ----------------
__device__ __forceinline__ uint32_t rotl32(uint32_t x, int r) {
    return (x << r) | (x >> (32 - r));
}
__device__ __forceinline__ uint32_t jax_random_bits(uint32_t idx) {
    const uint32_t ks0 = 0u;
    const uint32_t ks1 = 123u;
    const uint32_t ks2 = 0x1BD11BDAu ^ ks0 ^ ks1;
    uint32_t x0 = 0u + ks0;
    uint32_t x1 = idx + ks1;
#define TF_ROUND(r) { x0 += x1; x1 = rotl32(x1, (r)); x1 ^= x0; }
    TF_ROUND(13) TF_ROUND(15) TF_ROUND(26) TF_ROUND(6)
    x0 += ks1; x1 += ks2 + 1u;
    TF_ROUND(17) TF_ROUND(29) TF_ROUND(16) TF_ROUND(24)
    x0 += ks2; x1 += ks0 + 2u;
    TF_ROUND(13) TF_ROUND(15) TF_ROUND(26) TF_ROUND(6)
    x0 += ks0; x1 += ks1 + 3u;
    TF_ROUND(17) TF_ROUND(29) TF_ROUND(16) TF_ROUND(24)
    x0 += ks1; x1 += ks2 + 4u;
    TF_ROUND(13) TF_ROUND(15) TF_ROUND(26) TF_ROUND(6)
    x0 += ks2; x1 += ks0 + 5u;
#undef TF_ROUND
    return x0 ^ x1;
}

// ---------------- fused fp32 -> fp16 conversion (3 arrays, 1 launch) -------
__global__ void convert_all(const float* __restrict__ s0, __half* __restrict__ d0, int n0,
                            const float* __restrict__ s1, __half* __restrict__ d1, int n1,
                            const float* __restrict__ s2, __half* __restrict__ d2, int n2)
{
    int i = (blockIdx.x * blockDim.x + threadIdx.x) * 4;
    const float* s;
    __half* d;
    if (i < n0) { s = s0; d = d0; }
    else if (i < n0 + n1) { i -= n0; s = s1; d = d1; }
    else { i -= n0 + n1; if (i >= n2) return; s = s2; d = d2; }
    float4 v = *(const float4*)(s + i);
    *(__half2*)(d + i)     = __floats2half2_rn(v.x, v.y);
    *(__half2*)(d + i + 2) = __floats2half2_rn(v.z, v.w);
}

// ---------------- fp16 NT GEMM, 4-warp CTA, warp tile 64x32 ----------------
// C[M,N] = A[M,K] * B[N,K]^T  (all fp16, fp32 accum)
// Block tile 128x64, BK=32, 128 threads (4 warps 2x2, warp tile 64x32).
// Stage: [A 8KB][B 4KB] = 12KB; 3 stages = 36KB. 5 CTAs/SM.
// lowerOnly=0: 3D grid, z selects (B,C) pair (fused Q/K proj), fp16 out.
// lowerOnly=1: 1D grid of lower-triangle S tiles. The mainloop ALSO computes
//   the threefry dropout bits for this thread's own 64 outputs (2/iter,
//   woven into idle issue slots); the epilogue writes exp(s/32) with the
//   keep/drop decision encoded in the SIGN bit (0 above the diagonal).
#define STG 12288
#define GEMM_SMEM 36864

__global__ __launch_bounds__(128, 5)
void gemm_mma_f16(const __half* __restrict__ A,
                  const __half* __restrict__ B0, const __half* __restrict__ B1,
                  int K, float* __restrict__ Cf,
                  __half* __restrict__ C0, __half* __restrict__ C1,
                  int ldc, int lowerOnly)
{
    int bj, bi;
    const int bz = blockIdx.z;
    const int tid = threadIdx.x;

    if (lowerOnly) {
        // t -> (bi, bj): bi(bi+1) <= t < (bi+1)(bi+2), bj = t - bi(bi+1)
        int t = blockIdx.x;
        int b = (int)((sqrtf((float)(4 * t + 1)) - 1.0f) * 0.5f);
        while ((b + 1) * (b + 2) <= t) b++;
        while (b * (b + 1) > t) b--;
        bi = b;
        bj = t - b * (b + 1);
    } else {
        bj = blockIdx.x;
        bi = blockIdx.y;
    }

    const __half* B = bz ? B1 : B0;
    __half* Ch = bz ? C1 : C0;

    extern __shared__ char smem[];
    const uint32_t sBase = smem_u32(smem);

    // ---- loader: 6 x 16B chunks / thread / stage ---------------------------
    uint32_t aso[4], bso[2];
    size_t ago[4], bgo[2];
    #pragma unroll
    for (int i = 0; i < 4; i++) {
        int idx = tid + i * 128;            // 0..511
        int r = idx >> 2, c = idx & 3;
        aso[i] = (uint32_t)(r * 4 + (c ^ ((r >> 1) & 3))) * 16;
        ago[i] = (size_t)r * K + c * 8;
    }
    #pragma unroll
    for (int i = 0; i < 2; i++) {
        int idx = tid + i * 128;            // 0..255
        int r = idx >> 2, c = idx & 3;
        bso[i] = 8192u + (uint32_t)(r * 4 + (c ^ ((r >> 1) & 3))) * 16;
        bgo[i] = (size_t)r * K + c * 8;
    }
    const __half* gA = A + (size_t)(bi * 128) * K;
    const __half* gB = B + (size_t)(bj * 64) * K;

    const int lane = tid & 31, wid = tid >> 5;
    const int wm = wid & 1, wn = wid >> 1;     // 2 x 2 warp grid, warp 64x32
    const int lr = lane & 15, lg = lane >> 4;
    const int gq = lane >> 2, tig = lane & 3;

    // output coords for mask gen (S mode)
    const int orow = bi * 128 + wm * 64 + gq;      // + mi*16 + (q&2)*4
    const int ocol = bj * 64 + wn * 32 + tig * 2;  // + n8*8 + (q&1)

    float c[4][4][4];                           // [mi][ni*2+h][quad]
    #pragma unroll
    for (int i = 0; i < 4; i++)
        #pragma unroll
        for (int j = 0; j < 4; j++)
            #pragma unroll
            for (int q = 0; q < 4; q++) c[i][j][q] = 0.f;

    uint64_t keepm = 0;                         // 64 keep-bits (S mode only)
    const int NIT = K >> 5;

    auto load_slot = [&](int it, int slot) {
        const int k0 = it << 5;
        const uint32_t sS = sBase + slot * STG;
        #pragma unroll
        for (int i = 0; i < 4; i++) cp_async16(sS + aso[i], gA + k0 + ago[i]);
        #pragma unroll
        for (int i = 0; i < 2; i++) cp_async16(sS + bso[i], gB + k0 + bgo[i]);
    };

    load_slot(0, 0); cp_commit();
    load_slot(1, 1); cp_commit();

    int slot = 0;
    for (int it = 0; it < NIT; ++it) {
        cp_wait<1>();
        __syncthreads();
        if (it + 2 < NIT) {
            int ns = slot + 2; if (ns >= 3) ns -= 3;
            load_slot(it + 2, ns);
        }
        cp_commit();

        const uint32_t aS = sBase + slot * STG;
        const uint32_t bS = aS + 8192;

        #pragma unroll
        for (int s = 0; s < 2; ++s) {
            uint32_t ah[4][4], bh[2][4];
            #pragma unroll
            for (int ni = 0; ni < 2; ni++) {
                int r = wn * 32 + ni * 16 + lr;
                uint32_t off = r * 64 + (((2 * s + lg) ^ ((r >> 1) & 3)) * 16);
                ldsm4(bh[ni], bS + off);
            }
            #pragma unroll
            for (int mi = 0; mi < 4; mi++) {
                int r = wm * 64 + mi * 16 + lr;
                uint32_t off = r * 64 + (((2 * s + lg) ^ ((r >> 1) & 3)) * 16);
                ldsm4(ah[mi], aS + off);
            }
            #pragma unroll
            for (int mi = 0; mi < 4; mi++)
                #pragma unroll
                for (int ni = 0; ni < 2; ni++)
                    #pragma unroll
                    for (int h = 0; h < 2; h++)
                        mma16816(c[mi][ni * 2 + h], ah[mi], bh[ni][h], bh[ni][h + 2]);
        }

        // ---- interleaved threefry: 2 of this thread's 64 outputs per iter --
        if (lowerOnly) {
            #pragma unroll
            for (int u = 0; u < 2; u++) {
                int e = 2 * it + u;
                int mi = e >> 4, n8 = (e >> 2) & 3, q = e & 3;
                int rr = orow + mi * 16 + ((q & 2) << 2);
                int cc = ocol + n8 * 8 + (q & 1);
                uint32_t bits = jax_random_bits((uint32_t)rr * (uint32_t)T_SEQ +
                                                (uint32_t)cc);
                keepm |= (uint64_t)((bits >> 31) ^ 1u) << e;
            }
        }

        if (++slot == 3) slot = 0;
    }

    // ---- epilogue ----
    #pragma unroll
    for (int mi = 0; mi < 4; mi++) {
        #pragma unroll
        for (int n8 = 0; n8 < 4; n8++) {
            int row0 = bi * 128 + wm * 64 + mi * 16 + gq;
            int col  = bj * 64 + wn * 32 + n8 * 8 + tig * 2;
            float* cp = c[mi][n8];
            if (Cf) {
                // exp(s/32), causal zero, keep/drop in sign bit
                float2 v0, v1;
                int eb = mi * 16 + n8 * 4;
                float e0 = (col     > row0) ? 0.f : __expf(cp[0] * 0.03125f);
                float e1 = (col + 1 > row0) ? 0.f : __expf(cp[1] * 0.03125f);
                float e2 = (col     > row0 + 8) ? 0.f : __expf(cp[2] * 0.03125f);
                float e3 = (col + 1 > row0 + 8) ? 0.f : __expf(cp[3] * 0.03125f);
                v0.x = ((keepm >> (eb + 0)) & 1) ? e0 : -e0;
                v0.y = ((keepm >> (eb + 1)) & 1) ? e1 : -e1;
                v1.x = ((keepm >> (eb + 2)) & 1) ? e2 : -e2;
                v1.y = ((keepm >> (eb + 3)) & 1) ? e3 : -e3;
                *(float2*)(Cf + (size_t)row0 * ldc + col) = v0;
                *(float2*)(Cf + (size_t)(row0 + 8) * ldc + col) = v1;
            } else {
                *(__half2*)(Ch + (size_t)row0 * ldc + col) =
                    __floats2half2_rn(cp[0], cp[1]);
                *(__half2*)(Ch + (size_t)(row0 + 8) * ldc + col) =
                    __floats2half2_rn(cp[2], cp[3]);
            }
        }
    }
}

// ------------- Row normalize + dropout apply (vectorized, mem-bound) -------
// buf holds exp(s/32) with keep/drop in the sign bit (0 above diagonal;
// unwritten upper tiles hold poison -> masked by column index).
// sum |v| over valid cols = softmax denominator; out = v>0 ? v*2/sum : 0.
__global__ __launch_bounds__(256)
void norm_dropout_kernel(float* __restrict__ buf)
{
    int row = blockIdx.x;
    int tid = threadIdx.x;
    float* rp = buf + (size_t)row * T_SEQ;

    float4 v[4];
    float sum = 0.f;
#pragma unroll
    for (int t = 0; t < 4; t++) {
        int col = (tid + (t << 8)) << 2;            // float4-aligned column
        float4 w = *(const float4*)(rp + col);
        // mask invalid lanes (col+k > row): zero them (also kills poison)
        if (col + 0 > row) w.x = 0.f;
        if (col + 1 > row) w.y = 0.f;
        if (col + 2 > row) w.z = 0.f;
        if (col + 3 > row) w.w = 0.f;
        v[t] = w;
        sum += fabsf(w.x) + fabsf(w.y) + fabsf(w.z) + fabsf(w.w);
    }

    __shared__ float sred[8];
#pragma unroll
    for (int o = 16; o > 0; o >>= 1)
        sum += __shfl_xor_sync(0xffffffffu, sum, o);
    if ((tid & 31) == 0) sred[tid >> 5] = sum;
    __syncthreads();
    sum = 0.f;
#pragma unroll
    for (int w = 0; w < 8; w++) sum += sred[w];

    float inv = 2.0f / sum;                  // includes /(1-p), p=0.5
#pragma unroll
    for (int t = 0; t < 4; t++) {
        int col = (tid + (t << 8)) << 2;
        float4 w = v[t];
        float4 o;
        o.x = (w.x > 0.f) ? w.x * inv : 0.f;
        o.y = (w.y > 0.f) ? w.y * inv : 0.f;
        o.z = (w.z > 0.f) ? w.z * inv : 0.f;
        o.w = (w.w > 0.f) ? w.w * inv : 0.f;
        *(float4*)(rp + col) = o;
    }
}

// ---------------------------------------------------------------------------
extern "C" void kernel_launch(void* const* d_in, const int* in_sizes, int n_in,
                              void* d_out, int out_size)
{
    const float* x  = (const float*)d_in[0];
    const float* Wq = (const float*)d_in[1];
    const float* Wk = (const float*)d_in[2];
    float* out = (float*)d_out;

    __half *xh, *wqh, *wkh, *qh, *kh;
    cudaGetSymbolAddress((void**)&xh,  g_xh);
    cudaGetSymbolAddress((void**)&wqh, g_Wqh);
    cudaGetSymbolAddress((void**)&wkh, g_Wkh);
    cudaGetSymbolAddress((void**)&qh,  g_Qh);
    cudaGetSymbolAddress((void**)&kh,  g_Kh);

    cudaFuncSetAttribute(gemm_mma_f16, cudaFuncAttributeMaxDynamicSharedMemorySize, GEMM_SMEM);

    int n1 = T_SEQ * D_MODEL, n2 = D_MODEL * D_MODEL;
    int ntot = (n1 + 2 * n2) / 4;
    convert_all<<<(ntot + 255) / 256, 256>>>(x, xh, n1, Wq, wqh, n2, Wk, wkh, n2);

    // Fused Q/K projections: z=0 -> Q = x@Wq^T, z=1 -> K = x@Wk^T (fp16 outs)
    gemm_mma_f16<<<dim3(D_MODEL / 64, T_SEQ / 128, 2), 128, GEMM_SMEM>>>(
        xh, wqh, wkh, D_MODEL, nullptr, qh, kh, D_MODEL, 0);
    // S tiles (lower triangle, 1056): in-loop threefry + exp/sign epilogue
    gemm_mma_f16<<<dim3(1056, 1, 1), 128, GEMM_SMEM>>>(
        qh, kh, nullptr, D_MODEL, out, nullptr, nullptr, T_SEQ, 1);
    // Row normalization + dropout apply (pure memory, float4)
    norm_dropout_kernel<<<T_SEQ, 256>>>(out);
}

// round 16
// speedup vs baseline: 1.1104x; 1.1104x over previous
#include <cuda_runtime.h>
#include <cuda_fp16.h>
#include <cstdint>

#define T_SEQ 4096
#define D_MODEL 1024

// ---------------- scratch (__device__ globals; no allocs allowed) ----------
__device__ __half g_xh[T_SEQ * D_MODEL];
__device__ __half g_Wqh[D_MODEL * D_MODEL];
__device__ __half g_Wkh[D_MODEL * D_MODEL];
__device__ __half g_Qh[T_SEQ * D_MODEL];
__device__ __half g_Kh[T_SEQ * D_MODEL];

// ---------------- helpers ---------------------------------------------------
__device__ __forceinline__ uint32_t smem_u32(const void* p) {
    uint32_t a;
    asm("{ .reg .u64 t; cvta.to.shared.u64 t, %1; cvt.u32.u64 %0, t; }" : "=r"(a) : "l"(p));
    return a;
}
__device__ __forceinline__ void cp_async16(uint32_t s, const void* g) {
    asm volatile("cp.async.cg.shared.global [%0], [%1], 16;" :: "r"(s), "l"(g));
}
__device__ __forceinline__ void cp_commit() {
    asm volatile("cp.async.commit_group;" ::: "memory");
}
template <int N> __device__ __forceinline__ void cp_wait() {
    asm volatile("cp.async.wait_group %0;" :: "n"(N) : "memory");
}
__device__ __forceinline__ void ldsm4(uint32_t* r, uint32_t addr) {
    asm volatile("ldmatrix.sync.aligned.m8n8.x4.shared.b16 {%0,%1,%2,%3}, [%4];"
                 : "=r"(r[0]), "=r"(r[1]), "=r"(r[2]), "=r"(r[3]) : "r"(addr));
}
__device__ __forceinline__ void mma16816(float* c, const uint32_t* a, uint32_t b0, uint32_t b1) {
    asm volatile(
        "mma.sync.aligned.m16n8k16.row.col.f32.f16.f16.f32 "
        "{%0,%1,%2,%3}, {%4,%5,%6,%7}, {%8,%9}, {%0,%1,%2,%3};"
        : "+f"(c[0]), "+f"(c[1]), "+f"(c[2]), "+f"(c[3])
        : "r"(a[0]), "r"(a[1]), "r"(a[2]), "r"(a[3]), "r"(b0), "r"(b1));
}

// ---------------- Threefry-2x32-20 (JAX partitionable path) ----------------
__device__ __forceinline__ uint32_t rotl32(uint32_t x, int r) {
    return (x << r) | (x >> (32 - r));
}
__device__ __forceinline__ uint32_t jax_random_bits(uint32_t idx) {
    const uint32_t ks0 = 0u;
    const uint32_t ks1 = 123u;
    const uint32_t ks2 = 0x1BD11BDAu ^ ks0 ^ ks1;
    uint32_t x0 = 0u + ks0;
    uint32_t x1 = idx + ks1;
#define TF_ROUND(r) { x0 += x1; x1 = rotl32(x1, (r)); x1 ^= x0; }
    TF_ROUND(13) TF_ROUND(15) TF_ROUND(26) TF_ROUND(6)
    x0 += ks1; x1 += ks2 + 1u;
    TF_ROUND(17) TF_ROUND(29) TF_ROUND(16) TF_ROUND(24)
    x0 += ks2; x1 += ks0 + 2u;
    TF_ROUND(13) TF_ROUND(15) TF_ROUND(26) TF_ROUND(6)
    x0 += ks0; x1 += ks1 + 3u;
    TF_ROUND(17) TF_ROUND(29) TF_ROUND(16) TF_ROUND(24)
    x0 += ks1; x1 += ks2 + 4u;
    TF_ROUND(13) TF_ROUND(15) TF_ROUND(26) TF_ROUND(6)
    x0 += ks2; x1 += ks0 + 5u;
#undef TF_ROUND
    return x0 ^ x1;
}

// ---------------- fused fp32 -> fp16 conversion (3 arrays, 1 launch) -------
__global__ void convert_all(const float* __restrict__ s0, __half* __restrict__ d0, int n0,
                            const float* __restrict__ s1, __half* __restrict__ d1, int n1,
                            const float* __restrict__ s2, __half* __restrict__ d2, int n2)
{
    int i = (blockIdx.x * blockDim.x + threadIdx.x) * 4;
    const float* s;
    __half* d;
    if (i < n0) { s = s0; d = d0; }
    else if (i < n0 + n1) { i -= n0; s = s1; d = d1; }
    else { i -= n0 + n1; if (i >= n2) return; s = s2; d = d2; }
    float4 v = *(const float4*)(s + i);
    *(__half2*)(d + i)     = __floats2half2_rn(v.x, v.y);
    *(__half2*)(d + i + 2) = __floats2half2_rn(v.z, v.w);
}

// ---------------- fp16 NT GEMM, BK=64, 4-warp CTA, warp tile 64x32 ---------
// C[M,N] = A[M,K] * B[N,K]^T  (all fp16, fp32 accum)
// Block tile 128x64, BK=64, 128 threads (4 warps 2x2, warp tile 64x32).
// Stage: [A 16KB][B 8KB] = 24KB (128B rows, swizzle chunk^=(r&7));
// 3 stages = 72KB. 3 CTAs/SM.
// lowerOnly=0: 3D grid, z selects (B,C) pair (fused Q/K proj), fp16 out.
// lowerOnly=1: 1D grid of lower-triangle S tiles; in-loop threefry (4/iter),
//   epilogue writes exp(s/32) with keep/drop in the SIGN bit (0 above diag).
#define STG 24576
#define GEMM_SMEM 73728

__global__ __launch_bounds__(128, 3)
void gemm_mma_f16(const __half* __restrict__ A,
                  const __half* __restrict__ B0, const __half* __restrict__ B1,
                  int K, float* __restrict__ Cf,
                  __half* __restrict__ C0, __half* __restrict__ C1,
                  int ldc, int lowerOnly)
{
    int bj, bi;
    const int bz = blockIdx.z;
    const int tid = threadIdx.x;

    if (lowerOnly) {
        // t -> (bi, bj): bi(bi+1) <= t < (bi+1)(bi+2), bj = t - bi(bi+1)
        int t = blockIdx.x;
        int b = (int)((sqrtf((float)(4 * t + 1)) - 1.0f) * 0.5f);
        while ((b + 1) * (b + 2) <= t) b++;
        while (b * (b + 1) > t) b--;
        bi = b;
        bj = t - b * (b + 1);
    } else {
        bj = blockIdx.x;
        bi = blockIdx.y;
    }

    const __half* B = bz ? B1 : B0;
    __half* Ch = bz ? C1 : C0;

    extern __shared__ char smem[];
    const uint32_t sBase = smem_u32(smem);

    // ---- loader: 12 x 16B chunks / thread / stage (A:8, B:4) --------------
    // A: 128 rows x 8 chunks (128B rows); B: 64 rows x 8 chunks.
    // swizzle: chunk c ^= (r & 7)
    uint32_t aso[8], bso[4];
    uint32_t ago[8], bgo[4];
    #pragma unroll
    for (int i = 0; i < 8; i++) {
        int idx = tid + i * 128;            // 0..1023
        int r = idx >> 3, c = idx & 7;
        aso[i] = (uint32_t)(r * 128 + ((c ^ (r & 7)) * 16));
        ago[i] = (uint32_t)(r * K + c * 8);
    }
    #pragma unroll
    for (int i = 0; i < 4; i++) {
        int idx = tid + i * 128;            // 0..511
        int r = idx >> 3, c = idx & 7;
        bso[i] = 16384u + (uint32_t)(r * 128 + ((c ^ (r & 7)) * 16));
        bgo[i] = (uint32_t)(r * K + c * 8);
    }
    const __half* gA = A + (size_t)(bi * 128) * K;
    const __half* gB = B + (size_t)(bj * 64) * K;

    const int lane = tid & 31, wid = tid >> 5;
    const int wm = wid & 1, wn = wid >> 1;     // 2 x 2 warp grid, warp 64x32
    const int lr = lane & 15, lg = lane >> 4;
    const int gq = lane >> 2, tig = lane & 3;

    // output coords for mask gen (S mode)
    const int orow = bi * 128 + wm * 64 + gq;      // + mi*16 + (q&2)*4
    const int ocol = bj * 64 + wn * 32 + tig * 2;  // + n8*8 + (q&1)

    float c[4][4][4];                           // [mi][ni*2+h][quad]
    #pragma unroll
    for (int i = 0; i < 4; i++)
        #pragma unroll
        for (int j = 0; j < 4; j++)
            #pragma unroll
            for (int q = 0; q < 4; q++) c[i][j][q] = 0.f;

    uint64_t keepm = 0;                         // 64 keep-bits (S mode only)
    const int NIT = K >> 6;                     // BK = 64

    auto load_slot = [&](int it, int slot) {
        const int k0 = it << 6;
        const uint32_t sS = sBase + slot * STG;
        #pragma unroll
        for (int i = 0; i < 8; i++) cp_async16(sS + aso[i], gA + k0 + ago[i]);
        #pragma unroll
        for (int i = 0; i < 4; i++) cp_async16(sS + bso[i], gB + k0 + bgo[i]);
    };

    load_slot(0, 0); cp_commit();
    load_slot(1, 1); cp_commit();

    int slot = 0;
    for (int it = 0; it < NIT; ++it) {
        cp_wait<1>();
        __syncthreads();
        if (it + 2 < NIT) {
            int ns = slot + 2; if (ns >= 3) ns -= 3;
            load_slot(it + 2, ns);
        }
        cp_commit();

        const uint32_t aS = sBase + slot * STG;
        const uint32_t bS = aS + 16384;

        #pragma unroll
        for (int s = 0; s < 4; ++s) {
            uint32_t ah[4][4], bh[2][4];
            #pragma unroll
            for (int ni = 0; ni < 2; ni++) {
                int r = wn * 32 + ni * 16 + lr;
                uint32_t off = r * 128 + (((2 * s + lg) ^ (r & 7)) * 16);
                ldsm4(bh[ni], bS + off);
            }
            #pragma unroll
            for (int mi = 0; mi < 4; mi++) {
                int r = wm * 64 + mi * 16 + lr;
                uint32_t off = r * 128 + (((2 * s + lg) ^ (r & 7)) * 16);
                ldsm4(ah[mi], aS + off);
            }
            #pragma unroll
            for (int mi = 0; mi < 4; mi++)
                #pragma unroll
                for (int ni = 0; ni < 2; ni++)
                    #pragma unroll
                    for (int h = 0; h < 2; h++)
                        mma16816(c[mi][ni * 2 + h], ah[mi], bh[ni][h], bh[ni][h + 2]);
        }

        // ---- interleaved threefry: 4 of this thread's 64 outputs per iter --
        if (lowerOnly) {
            #pragma unroll
            for (int u = 0; u < 4; u++) {
                int e = 4 * it + u;
                int mi = e >> 4, n8 = (e >> 2) & 3, q = e & 3;
                int rr = orow + mi * 16 + ((q & 2) << 2);
                int cc = ocol + n8 * 8 + (q & 1);
                uint32_t bits = jax_random_bits((uint32_t)rr * (uint32_t)T_SEQ +
                                                (uint32_t)cc);
                keepm |= (uint64_t)((bits >> 31) ^ 1u) << e;
            }
        }

        if (++slot == 3) slot = 0;
    }

    // ---- epilogue ----
    #pragma unroll
    for (int mi = 0; mi < 4; mi++) {
        #pragma unroll
        for (int n8 = 0; n8 < 4; n8++) {
            int row0 = bi * 128 + wm * 64 + mi * 16 + gq;
            int col  = bj * 64 + wn * 32 + n8 * 8 + tig * 2;
            float* cp = c[mi][n8];
            if (Cf) {
                // exp(s/32), causal zero, keep/drop in sign bit
                float2 v0, v1;
                int eb = mi * 16 + n8 * 4;
                float e0 = (col     > row0) ? 0.f : __expf(cp[0] * 0.03125f);
                float e1 = (col + 1 > row0) ? 0.f : __expf(cp[1] * 0.03125f);
                float e2 = (col     > row0 + 8) ? 0.f : __expf(cp[2] * 0.03125f);
                float e3 = (col + 1 > row0 + 8) ? 0.f : __expf(cp[3] * 0.03125f);
                v0.x = ((keepm >> (eb + 0)) & 1) ? e0 : -e0;
                v0.y = ((keepm >> (eb + 1)) & 1) ? e1 : -e1;
                v1.x = ((keepm >> (eb + 2)) & 1) ? e2 : -e2;
                v1.y = ((keepm >> (eb + 3)) & 1) ? e3 : -e3;
                *(float2*)(Cf + (size_t)row0 * ldc + col) = v0;
                *(float2*)(Cf + (size_t)(row0 + 8) * ldc + col) = v1;
            } else {
                *(__half2*)(Ch + (size_t)row0 * ldc + col) =
                    __floats2half2_rn(cp[0], cp[1]);
                *(__half2*)(Ch + (size_t)(row0 + 8) * ldc + col) =
                    __floats2half2_rn(cp[2], cp[3]);
            }
        }
    }
}

// ------------- Row normalize + dropout apply (vectorized, mem-bound) -------
__global__ __launch_bounds__(256)
void norm_dropout_kernel(float* __restrict__ buf)
{
    int row = blockIdx.x;
    int tid = threadIdx.x;
    float* rp = buf + (size_t)row * T_SEQ;

    float4 v[4];
    float sum = 0.f;
#pragma unroll
    for (int t = 0; t < 4; t++) {
        int col = (tid + (t << 8)) << 2;            // float4-aligned column
        float4 w = *(const float4*)(rp + col);
        if (col + 0 > row) w.x = 0.f;
        if (col + 1 > row) w.y = 0.f;
        if (col + 2 > row) w.z = 0.f;
        if (col + 3 > row) w.w = 0.f;
        v[t] = w;
        sum += fabsf(w.x) + fabsf(w.y) + fabsf(w.z) + fabsf(w.w);
    }

    __shared__ float sred[8];
#pragma unroll
    for (int o = 16; o > 0; o >>= 1)
        sum += __shfl_xor_sync(0xffffffffu, sum, o);
    if ((tid & 31) == 0) sred[tid >> 5] = sum;
    __syncthreads();
    sum = 0.f;
#pragma unroll
    for (int w = 0; w < 8; w++) sum += sred[w];

    float inv = 2.0f / sum;                  // includes /(1-p), p=0.5
#pragma unroll
    for (int t = 0; t < 4; t++) {
        int col = (tid + (t << 8)) << 2;
        float4 w = v[t];
        float4 o;
        o.x = (w.x > 0.f) ? w.x * inv : 0.f;
        o.y = (w.y > 0.f) ? w.y * inv : 0.f;
        o.z = (w.z > 0.f) ? w.z * inv : 0.f;
        o.w = (w.w > 0.f) ? w.w * inv : 0.f;
        *(float4*)(rp + col) = o;
    }
}

// ---------------------------------------------------------------------------
extern "C" void kernel_launch(void* const* d_in, const int* in_sizes, int n_in,
                              void* d_out, int out_size)
{
    const float* x  = (const float*)d_in[0];
    const float* Wq = (const float*)d_in[1];
    const float* Wk = (const float*)d_in[2];
    float* out = (float*)d_out;

    __half *xh, *wqh, *wkh, *qh, *kh;
    cudaGetSymbolAddress((void**)&xh,  g_xh);
    cudaGetSymbolAddress((void**)&wqh, g_Wqh);
    cudaGetSymbolAddress((void**)&wkh, g_Wkh);
    cudaGetSymbolAddress((void**)&qh,  g_Qh);
    cudaGetSymbolAddress((void**)&kh,  g_Kh);

    cudaFuncSetAttribute(gemm_mma_f16, cudaFuncAttributeMaxDynamicSharedMemorySize, GEMM_SMEM);

    int n1 = T_SEQ * D_MODEL, n2 = D_MODEL * D_MODEL;
    int ntot = (n1 + 2 * n2) / 4;
    convert_all<<<(ntot + 255) / 256, 256>>>(x, xh, n1, Wq, wqh, n2, Wk, wkh, n2);

    // Fused Q/K projections: z=0 -> Q = x@Wq^T, z=1 -> K = x@Wk^T (fp16 outs)
    gemm_mma_f16<<<dim3(D_MODEL / 64, T_SEQ / 128, 2), 128, GEMM_SMEM>>>(
        xh, wqh, wkh, D_MODEL, nullptr, qh, kh, D_MODEL, 0);
    // S tiles (lower triangle, 1056): in-loop threefry + exp/sign epilogue
    gemm_mma_f16<<<dim3(1056, 1, 1), 128, GEMM_SMEM>>>(
        qh, kh, nullptr, D_MODEL, out, nullptr, nullptr, T_SEQ, 1);
    // Row normalization + dropout apply (pure memory, float4)
    norm_dropout_kernel<<<T_SEQ, 256>>>(out);
}